// round 4
// baseline (speedup 1.0000x reference)
#include <cuda_runtime.h>
#include <math.h>

// Problem constants
#define BB 2048
#define TT 200
#define DD 64
#define H1 80
#define H2 40
#define NTHR 1024

#define KTP   202   // kdup t-stride (ull); even -> 16B-aligned LDS.128 pairs
#define WES   772   // weff js-stride (floats): 772%32=4 -> distinct phases; %4==0 -> 16B align
#define WIS   12    // weff i-stride (floats), 10 data + 2 pad, %4==0
#define W2JS  6     // w2dup js-stride (ull)
#define W2RS  48    // w2dup j1-stride (ull); js*48B mod 128 all distinct
#define H1TS  202   // h1T j1-stride (floats)

// Shared memory layout (float offsets)
#define OFF_KDUP  0        // 64*202 ull = 25856 floats
#define OFF_H1T   0        // alias of kdup region (80*202 = 16160), used strictly after
#define OFF_WEFF  25856    // 8*772 = 6176
#define OFF_W2D   32032    // 80*48 ull = 7680 floats
#define OFF_Q     39712    // 64
#define OFF_C     39776    // 80
#define OFF_CP    39856    // 8*80 = 640
#define OFF_WF    40496    // 40
#define OFF_B2D   40536    // 40 ull = 80 floats
#define OFF_BF    40616    // 8
#define OFF_LBUF  40624    // 208
#define OFF_RBUF  40832    // 64
#define OFF_VPART 40896    // 1024
#define SMEM_FLOATS 41920
#define SMEM_BYTES  (SMEM_FLOATS * 4)

typedef unsigned long long ull;

// ---- packed f32x2 helpers (sm_100+; ptxas never auto-fuses) ----
__device__ __forceinline__ ull pack2(float lo, float hi) {
    ull r;
    asm("mov.b64 %0, {%1, %2};" : "=l"(r) : "r"(__float_as_uint(lo)), "r"(__float_as_uint(hi)));
    return r;
}
__device__ __forceinline__ void unpack2(ull v, float& lo, float& hi) {
    unsigned int a, b;
    asm("mov.b64 {%0, %1}, %2;" : "=r"(a), "=r"(b) : "l"(v));
    lo = __uint_as_float(a);
    hi = __uint_as_float(b);
}
__device__ __forceinline__ void fma2(ull& d, ull a, ull b) {
    asm("fma.rn.f32x2 %0, %1, %2, %0;" : "+l"(d) : "l"(a), "l"(b));
}

__global__ void __launch_bounds__(NTHR, 1)
din_attention_kernel(const float* __restrict__ q,
                     const float* __restrict__ k,
                     const float* __restrict__ v,
                     const float* __restrict__ W1,
                     const float* __restrict__ b1,
                     const float* __restrict__ a1,
                     const float* __restrict__ W2,
                     const float* __restrict__ b2,
                     const float* __restrict__ a2,
                     const float* __restrict__ Wf,
                     const float* __restrict__ bf,
                     float* __restrict__ out)
{
    extern __shared__ float sm[];
    ull*   kd    = reinterpret_cast<ull*>(sm + OFF_KDUP);
    ull*   w2d   = reinterpret_cast<ull*>(sm + OFF_W2D);
    float* lbuf  = sm + OFF_LBUF;
    float* rbuf  = sm + OFF_RBUF;
    float* vpart = sm + OFF_VPART;

    const int tid  = threadIdx.x;
    const int b    = blockIdx.x;
    const int lane = tid & 31;
    const int warp = tid >> 5;

    const int TG  = tid >> 3;                       // t-pair group 0..127
    const int JS  = tid & 7;                        // column slot 0..7
    const int TGC = (TG < TT / 2) ? TG : (TT / 2 - 1);
    const int t0  = 2 * TGC;

    // ---------------- Phase A: stage data ----------------
    if (tid < DD) sm[OFF_Q + tid] = q[(size_t)b * DD + tid];
    {
        // k -> kdup: transpose + duplicate, coalesced global reads
        const float* kb = k + (size_t)b * TT * DD;
        #pragma unroll
        for (int x = tid; x < TT * DD; x += NTHR) {
            int t = x >> 6, i = x & 63;
            float kv = kb[x];
            kd[i * KTP + t] = pack2(kv, kv);
        }
    }
    {
        // W2 -> w2dup (duplicated ull, js-blocked)
        for (int x = tid; x < H1 * H2; x += NTHR) {
            int j1 = x / H2, j2 = x - j1 * H2;
            float w = W2[x];
            w2d[j1 * W2RS + (j2 / 5) * W2JS + (j2 % 5)] = pack2(w, w);
        }
    }
    if (tid < H2) sm[OFF_WF + tid] = Wf[tid];
    if (tid >= 64 && tid < 64 + H2) {
        float bv = b2[tid - 64];
        reinterpret_cast<ull*>(sm + OFF_B2D)[tid - 64] = pack2(bv, bv);
    }
    if (tid == 128) sm[OFF_BF] = bf[0];
    __syncthreads();

    // ---------------- Phase B: per-batch effective weights + c partials ----------------
    // weff[js][i][jj] = (W1b - W1c)[i][j] + q[i]*W1d[i][j],  j = 10*js+jj
    for (int x = tid; x < DD * H1; x += NTHR) {
        int i = x / H1;
        int j = x - i * H1;
        float w = W1[(DD + i) * H1 + j]
                - W1[(2 * DD + i) * H1 + j]
                + sm[OFF_Q + i] * W1[(3 * DD + i) * H1 + j];
        sm[OFF_WEFF + (j / 10) * WES + i * WIS + (j % 10)] = w;
    }
    // c partials: 640 threads, each 8 i's for one j
    if (tid < 640) {
        int j  = tid % 80;
        int ch = tid / 80;          // 0..7
        float c = 0.f;
        #pragma unroll
        for (int i = ch * 8; i < ch * 8 + 8; i++)
            c += sm[OFF_Q + i] * (W1[i * H1 + j] + W1[(2 * DD + i) * H1 + j]);
        sm[OFF_CP + ch * 80 + j] = c;
    }
    __syncthreads();
    if (tid < H1) {
        float c = b1[tid];
        #pragma unroll
        for (int ch = 0; ch < 8; ch++) c += sm[OFF_CP + ch * 80 + tid];
        sm[OFF_C + tid] = c;
    }
    __syncthreads();

    // ---------------- Phase C: layer 1, 2t x 10j register tile ----------------
    ull h[2][5];   // [t][j-pair]
    {
        const ull* cp = reinterpret_cast<const ull*>(sm + OFF_C + 10 * JS);
        #pragma unroll
        for (int jp = 0; jp < 5; jp++) {
            ull cc = cp[jp];
            h[0][jp] = cc; h[1][jp] = cc;
        }
    }
    {
        const ull*   kr = kd + t0;
        const float* wb = sm + OFF_WEFF + JS * WES;
        #pragma unroll 8
        for (int i = 0; i < DD; i++) {
            ulonglong2 kk = *reinterpret_cast<const ulonglong2*>(kr + i * KTP); // (k_t0,k_t0),(k_t1,k_t1)
            const float* wrow = wb + i * WIS;
            ulonglong2 wA = *reinterpret_cast<const ulonglong2*>(wrow);
            ulonglong2 wB = *reinterpret_cast<const ulonglong2*>(wrow + 4);
            ull        wC = *reinterpret_cast<const ull*>(wrow + 8);
            fma2(h[0][0], kk.x, wA.x); fma2(h[0][1], kk.x, wA.y);
            fma2(h[0][2], kk.x, wB.x); fma2(h[0][3], kk.x, wB.y);
            fma2(h[0][4], kk.x, wC);
            fma2(h[1][0], kk.y, wA.x); fma2(h[1][1], kk.y, wA.y);
            fma2(h[1][2], kk.y, wB.x); fma2(h[1][3], kk.y, wB.y);
            fma2(h[1][4], kk.y, wC);
        }
    }

    // Prefetch a1 (L2) for both t's before the barrier
    float2 a1r0[5], a1r1[5];
    {
        const float2* p0 = reinterpret_cast<const float2*>(a1 + (t0)     * H1 + 10 * JS);
        const float2* p1 = reinterpret_cast<const float2*>(a1 + (t0 + 1) * H1 + 10 * JS);
        #pragma unroll
        for (int jp = 0; jp < 5; jp++) { a1r0[jp] = __ldg(p0 + jp); a1r1[jp] = __ldg(p1 + jp); }
    }

    __syncthreads();   // all warps done reading kdup; safe to overwrite with h1T

    // PReLU 1 fused with transposed store h1T[j1][t]
    {
        float* hb = sm + OFF_H1T;
        #pragma unroll
        for (int jp = 0; jp < 5; jp++) {
            float x00, x01; unpack2(h[0][jp], x00, x01);  // t0: j=2jp, 2jp+1
            float x10, x11; unpack2(h[1][jp], x10, x11);  // t1
            float2 A0 = a1r0[jp], A1 = a1r1[jp];
            x00 = (x00 > 0.f) ? x00 : A0.x * x00;
            x01 = (x01 > 0.f) ? x01 : A0.y * x01;
            x10 = (x10 > 0.f) ? x10 : A1.x * x10;
            x11 = (x11 > 0.f) ? x11 : A1.y * x11;
            int j1a = 10 * JS + 2 * jp;
            *reinterpret_cast<float2*>(hb + j1a * H1TS + t0)       = make_float2(x00, x10);
            *reinterpret_cast<float2*>(hb + (j1a + 1) * H1TS + t0) = make_float2(x01, x11);
        }
    }
    __syncthreads();

    // ---------------- Phase D: layer 2, 2t x 5j2 register tile ----------------
    // Prefetch a2 + wf for the epilogue
    float a2r0[5], a2r1[5], wfr[5];
    {
        const int j2b = 5 * JS;
        #pragma unroll
        for (int c = 0; c < 5; c++) {
            a2r0[c] = __ldg(a2 + (t0)     * H2 + j2b + c);
            a2r1[c] = __ldg(a2 + (t0 + 1) * H2 + j2b + c);
            wfr[c]  = sm[OFF_WF + j2b + c];
        }
    }

    ull g[5];
    {
        const ull* b2p = reinterpret_cast<const ull*>(sm + OFF_B2D) + 5 * JS;
        #pragma unroll
        for (int c = 0; c < 5; c++) g[c] = b2p[c];
    }
    {
        const float* hb = sm + OFF_H1T + t0;
        const ull*   wr = w2d + JS * W2JS;
        #pragma unroll 8
        for (int j1 = 0; j1 < H1; j1++) {
            ull h01 = *reinterpret_cast<const ull*>(hb + j1 * H1TS);   // (h[t0], h[t1])
            const ull* wp = wr + j1 * W2RS;
            ulonglong2 wA = *reinterpret_cast<const ulonglong2*>(wp);
            ulonglong2 wB = *reinterpret_cast<const ulonglong2*>(wp + 2);
            ull        wC = wp[4];
            fma2(g[0], h01, wA.x); fma2(g[1], h01, wA.y);
            fma2(g[2], h01, wB.x); fma2(g[3], h01, wB.y);
            fma2(g[4], h01, wC);
        }
    }

    // PReLU 2 + final dot; reduce partial logits over the 8 JS lanes
    {
        float lg0 = 0.f, lg1 = 0.f;
        #pragma unroll
        for (int c = 0; c < 5; c++) {
            float x0, x1; unpack2(g[c], x0, x1);
            x0 = (x0 > 0.f) ? x0 : a2r0[c] * x0;
            x1 = (x1 > 0.f) ? x1 : a2r1[c] * x1;
            float w = wfr[c];
            lg0 += x0 * w; lg1 += x1 * w;
        }
        #pragma unroll
        for (int o = 1; o < 8; o <<= 1) {
            lg0 += __shfl_xor_sync(0xffffffffu, lg0, o);
            lg1 += __shfl_xor_sync(0xffffffffu, lg1, o);
        }
        if (JS == 0 && TG == TGC) {
            float bfv = sm[OFF_BF];
            *reinterpret_cast<float2*>(lbuf + t0) = make_float2(lg0 + bfv, lg1 + bfv);
        }
    }
    __syncthreads();

    // ---------------- Phase E: softmax over T ----------------
    const bool valid = (tid < TT);
    float logit = valid ? lbuf[tid] : -3.4e38f;
    float x = logit;
    #pragma unroll
    for (int o = 16; o; o >>= 1) x = fmaxf(x, __shfl_xor_sync(0xffffffffu, x, o));
    if (lane == 0) rbuf[warp] = x;
    __syncthreads();
    if (warp == 0) {
        float y = rbuf[lane];
        #pragma unroll
        for (int o = 16; o; o >>= 1) y = fmaxf(y, __shfl_xor_sync(0xffffffffu, y, o));
        if (lane == 0) rbuf[0] = y;
    }
    __syncthreads();
    const float m = rbuf[0];

    float e = valid ? __expf(logit - m) : 0.f;
    float s = e;
    #pragma unroll
    for (int o = 16; o; o >>= 1) s += __shfl_xor_sync(0xffffffffu, s, o);
    if (lane == 0) rbuf[32 + warp] = s;
    __syncthreads();
    if (warp == 0) {
        float y = rbuf[32 + lane];
        #pragma unroll
        for (int o = 16; o; o >>= 1) y += __shfl_xor_sync(0xffffffffu, y, o);
        if (lane == 0) rbuf[32] = y;
    }
    __syncthreads();
    const float inv = 1.f / rbuf[32];
    if (valid) lbuf[tid] = e * inv;
    __syncthreads();

    // ---------------- Phase F: out[b][d] = sum_t w[t] * v[b][t][d] ----------------
    {
        const int d   = tid & 63;
        const int grp = tid >> 6;   // 0..15
        const float* vb = v + (size_t)b * TT * DD;
        float acc = 0.f;
        for (int t2 = grp; t2 < TT; t2 += 16)
            acc += lbuf[t2] * vb[t2 * DD + d];
        vpart[tid] = acc;
    }
    __syncthreads();
    if (tid < DD) {
        float r = 0.f;
        #pragma unroll
        for (int g2 = 0; g2 < 16; g2++) r += vpart[g2 * 64 + tid];
        out[(size_t)b * DD + tid] = r;
    }
}

extern "C" void kernel_launch(void* const* d_in, const int* in_sizes, int n_in,
                              void* d_out, int out_size)
{
    const float* q  = (const float*)d_in[0];
    const float* k  = (const float*)d_in[1];
    const float* v  = (const float*)d_in[2];
    const float* W1 = (const float*)d_in[3];
    const float* b1 = (const float*)d_in[4];
    const float* a1 = (const float*)d_in[5];
    const float* W2 = (const float*)d_in[6];
    const float* b2 = (const float*)d_in[7];
    const float* a2 = (const float*)d_in[8];
    const float* Wf = (const float*)d_in[9];
    const float* bf = (const float*)d_in[10];
    float* out = (float*)d_out;

    cudaFuncSetAttribute(din_attention_kernel,
                         cudaFuncAttributeMaxDynamicSharedMemorySize, SMEM_BYTES);
    din_attention_kernel<<<BB, NTHR, SMEM_BYTES>>>(q, k, v, W1, b1, a1, W2, b2, a2, Wf, bf, out);
}

// round 5
// speedup vs baseline: 1.6469x; 1.6469x over previous
#include <cuda_runtime.h>
#include <math.h>

// Problem constants
#define BB 2048
#define TT 200
#define DD 64
#define H1 80
#define H2 40
#define NTHR 512

#define KPAD 65    // k rows: bank = (65t+i)%32 -> conflict-free scalar loads
#define WES  772   // weff js-stride (floats): %4==0 (16B align), 772%32=4 -> distinct phases
#define WIS  12    // weff i-stride: 10 data + 2 pad, 16B-aligned rows
#define H1TS 200   // h1T j1-stride

// Shared memory layout (float offsets)
#define OFF_KBUF  0        // 200*65 = 13000
#define OFF_WEFF  13000    // 8*772 = 6176 -> ends 19176
#define OFF_H1T   0        // 80*200 = 16000, aliases kbuf+weff (dead after layer 1)
#define OFF_W2    19176    // 3200
#define OFF_Q     22376    // 64
#define OFF_C     22440    // 80
#define OFF_CP    22520    // 4*80 = 320
#define OFF_WF    22840    // 40
#define OFF_B2    22880    // 40
#define OFF_BF    22920    // 8
#define OFF_LBUF  22928    // 208
#define OFF_RBUF  23136    // 48
#define OFF_VPART 23184    // 512
#define SMEM_FLOATS 23696
#define SMEM_BYTES  (SMEM_FLOATS * 4)

typedef unsigned long long ull;

// ---- packed f32x2 helpers (sm_100+; ptxas never auto-fuses) ----
__device__ __forceinline__ ull pack2(float lo, float hi) {
    ull r;
    asm("mov.b64 %0, {%1, %2};" : "=l"(r) : "r"(__float_as_uint(lo)), "r"(__float_as_uint(hi)));
    return r;
}
__device__ __forceinline__ void unpack2(ull v, float& lo, float& hi) {
    unsigned int a, b;
    asm("mov.b64 {%0, %1}, %2;" : "=r"(a), "=r"(b) : "l"(v));
    lo = __uint_as_float(a);
    hi = __uint_as_float(b);
}
__device__ __forceinline__ void fma2(ull& d, ull a, ull b) {
    asm("fma.rn.f32x2 %0, %1, %2, %0;" : "+l"(d) : "l"(a), "l"(b));
}

__global__ void __launch_bounds__(NTHR, 1)
din_attention_kernel(const float* __restrict__ q,
                     const float* __restrict__ k,
                     const float* __restrict__ v,
                     const float* __restrict__ W1,
                     const float* __restrict__ b1,
                     const float* __restrict__ a1,
                     const float* __restrict__ W2,
                     const float* __restrict__ b2,
                     const float* __restrict__ a2,
                     const float* __restrict__ Wf,
                     const float* __restrict__ bf,
                     float* __restrict__ out)
{
    extern __shared__ float sm[];
    float* lbuf  = sm + OFF_LBUF;
    float* rbuf  = sm + OFF_RBUF;
    float* vpart = sm + OFF_VPART;

    const int tid  = threadIdx.x;
    const int b    = blockIdx.x;
    const int lane = tid & 31;
    const int warp = tid >> 5;

    const int TG  = tid >> 3;            // t-group 0..63
    const int JS  = tid & 7;             // column slot 0..7
    const int TGC = (TG < TT / 4) ? TG : (TT / 4 - 1);
    const int t0  = 4 * TGC;

    // ---------------- Region 0: q + everything not needing q ----------------
    if (tid < DD) sm[OFF_Q + tid] = q[(size_t)b * DD + tid];
    {
        const float4* kb4 = reinterpret_cast<const float4*>(k + (size_t)b * TT * DD);
        #pragma unroll 5
        for (int x = tid; x < TT * DD / 4; x += NTHR) {
            float4 vv = kb4[x];
            int t = x >> 4;
            int i = (x & 15) * 4;
            float* dst = sm + OFF_KBUF + t * KPAD + i;
            dst[0] = vv.x; dst[1] = vv.y; dst[2] = vv.z; dst[3] = vv.w;
        }
    }
    for (int idx = tid; idx < H1 * H2; idx += NTHR) sm[OFF_W2 + idx] = W2[idx];
    if (tid < H2) sm[OFF_WF + tid] = Wf[tid];
    if (tid >= 64 && tid < 64 + H2) sm[OFF_B2 + tid - 64] = b2[tid - 64];
    if (tid == 128) sm[OFF_BF] = bf[0];
    __syncthreads();   // q ready

    // ---------------- Region 1: weff build + c partials ----------------
    #pragma unroll 10
    for (int x = tid; x < DD * H1; x += NTHR) {
        int i = x / H1;
        int j = x - i * H1;
        float w = W1[(DD + i) * H1 + j]
                - W1[(2 * DD + i) * H1 + j]
                + sm[OFF_Q + i] * W1[(3 * DD + i) * H1 + j];
        sm[OFF_WEFF + (j / 10) * WES + i * WIS + (j % 10)] = w;
    }
    if (tid < 320) {
        int j  = tid % 80;
        int ch = tid / 80;          // 0..3
        float c = 0.f;
        #pragma unroll
        for (int i = ch * 16; i < ch * 16 + 16; i++)
            c += sm[OFF_Q + i] * (W1[i * H1 + j] + W1[(2 * DD + i) * H1 + j]);
        sm[OFF_CP + ch * 80 + j] = c;
    }
    __syncthreads();
    if (tid < H1) {
        sm[OFF_C + tid] = b1[tid] + sm[OFF_CP + tid] + sm[OFF_CP + 80 + tid]
                        + sm[OFF_CP + 160 + tid] + sm[OFF_CP + 240 + tid];
    }
    __syncthreads();

    // Prefetch a1 (L2) early — latency hidden under the whole layer-1 loop
    float2 a1r[4][5];
    {
        #pragma unroll
        for (int tt = 0; tt < 4; tt++) {
            const float2* ap = reinterpret_cast<const float2*>(a1 + (t0 + tt) * H1 + 10 * JS);
            #pragma unroll
            for (int jp = 0; jp < 5; jp++) a1r[tt][jp] = __ldg(ap + jp);
        }
    }

    // ---------------- Layer 1: 4t x 10j register tile ----------------
    ull h[20];  // h[tt*5 + jp]
    {
        const ull* cp = reinterpret_cast<const ull*>(sm + OFF_C + 10 * JS);
        #pragma unroll
        for (int jp = 0; jp < 5; jp++) {
            ull cc = cp[jp];
            h[jp] = cc; h[5 + jp] = cc; h[10 + jp] = cc; h[15 + jp] = cc;
        }
    }
    {
        const float* kb = sm + OFF_KBUF + t0 * KPAD;
        const float* wb = sm + OFF_WEFF + JS * WES;
        #pragma unroll 4
        for (int i = 0; i < DD; i++) {
            float k0 = kb[i];
            float k1 = kb[KPAD + i];
            float k2 = kb[2 * KPAD + i];
            float k3 = kb[3 * KPAD + i];
            const float* wrow = wb + i * WIS;
            ulonglong2 wA = *reinterpret_cast<const ulonglong2*>(wrow);      // j 0..3
            ulonglong2 wB = *reinterpret_cast<const ulonglong2*>(wrow + 4);  // j 4..7
            ull        wC = *reinterpret_cast<const ull*>(wrow + 8);         // j 8..9
            ull kk0 = pack2(k0, k0), kk1 = pack2(k1, k1);
            ull kk2 = pack2(k2, k2), kk3 = pack2(k3, k3);
            fma2(h[0],  kk0, wA.x); fma2(h[5],  kk1, wA.x); fma2(h[10], kk2, wA.x); fma2(h[15], kk3, wA.x);
            fma2(h[1],  kk0, wA.y); fma2(h[6],  kk1, wA.y); fma2(h[11], kk2, wA.y); fma2(h[16], kk3, wA.y);
            fma2(h[2],  kk0, wB.x); fma2(h[7],  kk1, wB.x); fma2(h[12], kk2, wB.x); fma2(h[17], kk3, wB.x);
            fma2(h[3],  kk0, wB.y); fma2(h[8],  kk1, wB.y); fma2(h[13], kk2, wB.y); fma2(h[18], kk3, wB.y);
            fma2(h[4],  kk0, wC);   fma2(h[9],  kk1, wC);   fma2(h[14], kk2, wC);   fma2(h[19], kk3, wC);
        }
    }

    // PReLU 1
    float h1v[4][10];
    #pragma unroll
    for (int tt = 0; tt < 4; tt++) {
        #pragma unroll
        for (int jp = 0; jp < 5; jp++) {
            float lo, hi; unpack2(h[tt * 5 + jp], lo, hi);
            float2 av = a1r[tt][jp];
            h1v[tt][2 * jp]     = (lo > 0.f) ? lo : av.x * lo;
            h1v[tt][2 * jp + 1] = (hi > 0.f) ? hi : av.y * hi;
        }
    }

    __syncthreads();   // kbuf + weff dead; safe to overwrite with h1T
    {
        float* hb = sm + OFF_H1T;
        #pragma unroll
        for (int jj = 0; jj < 10; jj++) {
            float4 vv = make_float4(h1v[0][jj], h1v[1][jj], h1v[2][jj], h1v[3][jj]);
            *reinterpret_cast<float4*>(hb + (10 * JS + jj) * H1TS + 4 * TGC) = vv;
        }
    }
    __syncthreads();

    // Prefetch a2 + wf before layer 2
    float a2r0[5], a2r1[5], a2r2[5], a2r3[5], wfr[5];
    {
        const int j2b = 5 * JS;
        #pragma unroll
        for (int c = 0; c < 5; c++) {
            a2r0[c] = __ldg(a2 + (t0 + 0) * H2 + j2b + c);
            a2r1[c] = __ldg(a2 + (t0 + 1) * H2 + j2b + c);
            a2r2[c] = __ldg(a2 + (t0 + 2) * H2 + j2b + c);
            a2r3[c] = __ldg(a2 + (t0 + 3) * H2 + j2b + c);
            wfr[c]  = sm[OFF_WF + j2b + c];
        }
    }

    // ---------------- Layer 2: 4t x 5j2 register tile ----------------
    ull g0[5], g1[5];
    {
        const float* b2p = sm + OFF_B2 + 5 * JS;
        #pragma unroll
        for (int c = 0; c < 5; c++) {
            ull bb = pack2(b2p[c], b2p[c]);
            g0[c] = bb; g1[c] = bb;
        }
    }
    {
        const float* hb2 = sm + OFF_H1T + 4 * TGC;
        const float* w2b = sm + OFF_W2 + 5 * JS;
        #pragma unroll 4
        for (int j1 = 0; j1 < H1; j1++) {
            ulonglong2 hh = *reinterpret_cast<const ulonglong2*>(hb2 + j1 * H1TS);
            const float* wp = w2b + j1 * H2;
            float w0 = wp[0], w1 = wp[1], w2v = wp[2], w3 = wp[3], w4 = wp[4];
            fma2(g0[0], hh.x, pack2(w0, w0)); fma2(g1[0], hh.y, pack2(w0, w0));
            fma2(g0[1], hh.x, pack2(w1, w1)); fma2(g1[1], hh.y, pack2(w1, w1));
            fma2(g0[2], hh.x, pack2(w2v, w2v)); fma2(g1[2], hh.y, pack2(w2v, w2v));
            fma2(g0[3], hh.x, pack2(w3, w3)); fma2(g1[3], hh.y, pack2(w3, w3));
            fma2(g0[4], hh.x, pack2(w4, w4)); fma2(g1[4], hh.y, pack2(w4, w4));
        }
    }

    // PReLU 2 + final dot; reduce partial logits over the 8 JS lanes
    {
        float lg0 = 0.f, lg1 = 0.f, lg2 = 0.f, lg3 = 0.f;
        #pragma unroll
        for (int c = 0; c < 5; c++) {
            float x0, x1; unpack2(g0[c], x0, x1);   // t0, t1
            float x2, x3; unpack2(g1[c], x2, x3);   // t2, t3
            x0 = (x0 > 0.f) ? x0 : a2r0[c] * x0;
            x1 = (x1 > 0.f) ? x1 : a2r1[c] * x1;
            x2 = (x2 > 0.f) ? x2 : a2r2[c] * x2;
            x3 = (x3 > 0.f) ? x3 : a2r3[c] * x3;
            float w = wfr[c];
            lg0 += x0 * w; lg1 += x1 * w; lg2 += x2 * w; lg3 += x3 * w;
        }
        #pragma unroll
        for (int o = 1; o < 8; o <<= 1) {
            lg0 += __shfl_xor_sync(0xffffffffu, lg0, o);
            lg1 += __shfl_xor_sync(0xffffffffu, lg1, o);
            lg2 += __shfl_xor_sync(0xffffffffu, lg2, o);
            lg3 += __shfl_xor_sync(0xffffffffu, lg3, o);
        }
        if (JS == 0 && TG == TGC) {
            float bfv = sm[OFF_BF];
            *reinterpret_cast<float4*>(lbuf + 4 * TGC) =
                make_float4(lg0 + bfv, lg1 + bfv, lg2 + bfv, lg3 + bfv);
        }
    }
    __syncthreads();

    // ---------------- Softmax over T ----------------
    const bool valid = (tid < TT);
    float logit = valid ? lbuf[tid] : -3.4e38f;
    float x = logit;
    #pragma unroll
    for (int o = 16; o; o >>= 1) x = fmaxf(x, __shfl_xor_sync(0xffffffffu, x, o));
    if (lane == 0) rbuf[warp] = x;
    __syncthreads();
    if (warp == 0) {
        float y = (lane < 16) ? rbuf[lane] : -3.4e38f;
        #pragma unroll
        for (int o = 8; o; o >>= 1) y = fmaxf(y, __shfl_xor_sync(0xffffffffu, y, o));
        if (lane == 0) rbuf[0] = y;
    }
    __syncthreads();
    const float m = rbuf[0];

    float e = valid ? __expf(logit - m) : 0.f;
    float s = e;
    #pragma unroll
    for (int o = 16; o; o >>= 1) s += __shfl_xor_sync(0xffffffffu, s, o);
    if (lane == 0) rbuf[16 + warp] = s;
    __syncthreads();
    if (warp == 0) {
        float y = (lane < 16) ? rbuf[16 + lane] : 0.f;
        #pragma unroll
        for (int o = 8; o; o >>= 1) y += __shfl_xor_sync(0xffffffffu, y, o);
        if (lane == 0) rbuf[16] = y;
    }
    __syncthreads();
    const float inv = 1.f / rbuf[16];
    if (valid) lbuf[tid] = e * inv;
    __syncthreads();

    // ---------------- out[b][d] = sum_t w[t] * v[b][t][d] ----------------
    {
        const int d   = tid & 63;
        const int grp = tid >> 6;   // 0..7
        const float* vb = v + (size_t)b * TT * DD;
        float acc = 0.f;
        #pragma unroll 5
        for (int t2 = grp; t2 < TT; t2 += 8)
            acc += lbuf[t2] * vb[t2 * DD + d];
        vpart[tid] = acc;
    }
    __syncthreads();
    if (tid < DD) {
        float r = 0.f;
        #pragma unroll
        for (int g2 = 0; g2 < 8; g2++) r += vpart[g2 * 64 + tid];
        out[(size_t)b * DD + tid] = r;
    }
}

extern "C" void kernel_launch(void* const* d_in, const int* in_sizes, int n_in,
                              void* d_out, int out_size)
{
    const float* q  = (const float*)d_in[0];
    const float* k  = (const float*)d_in[1];
    const float* v  = (const float*)d_in[2];
    const float* W1 = (const float*)d_in[3];
    const float* b1 = (const float*)d_in[4];
    const float* a1 = (const float*)d_in[5];
    const float* W2 = (const float*)d_in[6];
    const float* b2 = (const float*)d_in[7];
    const float* a2 = (const float*)d_in[8];
    const float* Wf = (const float*)d_in[9];
    const float* bf = (const float*)d_in[10];
    float* out = (float*)d_out;

    cudaFuncSetAttribute(din_attention_kernel,
                         cudaFuncAttributeMaxDynamicSharedMemorySize, SMEM_BYTES);
    din_attention_kernel<<<BB, NTHR, SMEM_BYTES>>>(q, k, v, W1, b1, a1, W2, b2, a2, Wf, bf, out);
}

// round 7
// speedup vs baseline: 1.6924x; 1.0276x over previous
#include <cuda_runtime.h>
#include <math.h>

// Problem constants
#define BB 2048
#define TT 200
#define DD 64
#define H1 80
#define H2 40
#define NTHR 224

#define KTRS 204   // k_tr i-row stride (floats): %4==0 -> 16B-aligned LDS.128
#define WES  772   // weff slot stride: %4==0, 772%32=4 -> banks 4*JS distinct
#define WIS  12    // weff i-stride within slot (10 data + 2 pad)
#define H1TS 204   // h1T row stride

// Shared memory layout (float offsets)
#define OFF_KTR   0        // 64*204 = 13056
#define OFF_WEFF  13056    // 8*772 = 6176 -> 19232
#define OFF_H1T   0        // 80*204 = 16320, aliases ktr (+weff head); both dead after layer 1
#define OFF_W2P   19232    // 3200 -> 22432 (row-permuted W2)
#define OFF_Q     22432    // 64
#define OFF_C     22496    // 80
#define OFF_CP    22576    // 160
#define OFF_WF    22736    // 40
#define OFF_B2    22776    // 40
#define OFF_BF    22816    // 8
#define OFF_LBUF  22824    // 208 (16B aligned)
#define OFF_RBUF  23032    // 32
#define OFF_VPART 23064    // 192
#define SMEM_FLOATS 23256
#define SMEM_BYTES  (SMEM_FLOATS * 4)

typedef unsigned long long ull;

// ---- packed f32x2 helpers (sm_100+; ptxas never auto-fuses) ----
__device__ __forceinline__ ull pack2(float lo, float hi) {
    ull r;
    asm("mov.b64 %0, {%1, %2};" : "=l"(r) : "r"(__float_as_uint(lo)), "r"(__float_as_uint(hi)));
    return r;
}
__device__ __forceinline__ void unpack2(ull v, float& lo, float& hi) {
    unsigned int a, b;
    asm("mov.b64 {%0, %1}, %2;" : "=r"(a), "=r"(b) : "l"(v));
    lo = __uint_as_float(a);
    hi = __uint_as_float(b);
}
__device__ __forceinline__ void fma2(ull& d, ull a, ull b) {
    asm("fma.rn.f32x2 %0, %1, %2, %0;" : "+l"(d) : "l"(a), "l"(b));
}

__global__ void __launch_bounds__(NTHR, 2)
din_attention_kernel(const float* __restrict__ q,
                     const float* __restrict__ k,
                     const float* __restrict__ v,
                     const float* __restrict__ W1,
                     const float* __restrict__ b1,
                     const float* __restrict__ a1,
                     const float* __restrict__ W2,
                     const float* __restrict__ b2,
                     const float* __restrict__ a2,
                     const float* __restrict__ Wf,
                     const float* __restrict__ bf,
                     float* __restrict__ out)
{
    extern __shared__ float sm[];
    float* lbuf  = sm + OFF_LBUF;
    float* rbuf  = sm + OFF_RBUF;
    float* vpart = sm + OFF_VPART;

    const int tid  = threadIdx.x;
    const int b    = blockIdx.x;
    const int lane = tid & 31;
    const int warp = tid >> 5;

    const int TG  = tid >> 3;                        // t-group 0..27 (8 t each)
    const int JS  = tid & 7;                         // j-slot 0..7 (10 j1 each)
    const int TGC = (TG < TT / 8) ? TG : (TT / 8 - 1);
    const int t0  = 8 * TGC;

    // ---------------- Phase A: stage data ----------------
    if (tid < DD) sm[OFF_Q + tid] = q[(size_t)b * DD + tid];
    {
        // k -> k_tr[i][t] transpose (coalesced reads)
        const float* kb = k + (size_t)b * TT * DD;
        #pragma unroll 4
        for (int x = tid; x < TT * DD; x += NTHR) {
            int t = x >> 6, i = x & 63;
            sm[OFF_KTR + i * KTRS + t] = kb[x];
        }
    }
    {
        // W2 -> row-permuted w2p: physical row pj holds logical j1 = 10*(pj%8) + pj/8
        for (int x = tid; x < H1 * H2; x += NTHR) {
            int pj = x / H2, j2 = x - pj * H2;
            int j1 = 10 * (pj & 7) + (pj >> 3);
            sm[OFF_W2P + x] = W2[j1 * H2 + j2];
        }
    }
    if (tid < H2) sm[OFF_WF + tid] = Wf[tid];
    if (tid >= 64 && tid < 64 + H2) sm[OFF_B2 + tid - 64] = b2[tid - 64];
    if (tid == 104) sm[OFF_BF] = bf[0];
    __syncthreads();   // q ready

    // ---------------- Phase B: weff + c partials ----------------
    // weff[slot js][i][jj] for j1 = 10*js + jj
    #pragma unroll 4
    for (int x = tid; x < DD * H1; x += NTHR) {
        int i = x / H1;
        int j = x - i * H1;
        float w = W1[(DD + i) * H1 + j]
                - W1[(2 * DD + i) * H1 + j]
                + sm[OFF_Q + i] * W1[(3 * DD + i) * H1 + j];
        sm[OFF_WEFF + (j / 10) * WES + i * WIS + (j % 10)] = w;
    }
    if (tid < 160) {
        int j  = tid % 80;
        int ch = tid / 80;          // 0..1
        float c = 0.f;
        #pragma unroll
        for (int i = ch * 32; i < ch * 32 + 32; i++)
            c += sm[OFF_Q + i] * (W1[i * H1 + j] + W1[(2 * DD + i) * H1 + j]);
        sm[OFF_CP + ch * 80 + j] = c;
    }
    __syncthreads();
    if (tid < H1)
        sm[OFF_C + tid] = b1[tid] + sm[OFF_CP + tid] + sm[OFF_CP + 80 + tid];
    __syncthreads();

    // ---------------- Layer 1: 8t x 10j tile, h packed over t-pairs ----------------
    ull h[40];   // h[tp*10 + j], tp = t-pair 0..3, j1 = 10*JS + j
    {
        const float* cb = sm + OFF_C + 10 * JS;
        #pragma unroll
        for (int j = 0; j < 10; j++) {
            float cv = cb[j];
            ull cc = pack2(cv, cv);
            h[j] = cc; h[10 + j] = cc; h[20 + j] = cc; h[30 + j] = cc;
        }
    }
    {
        const float* kro = sm + OFF_KTR + t0;
        const float* wro = sm + OFF_WEFF + JS * WES;
        #pragma unroll 2
        for (int i = 0; i < DD; i++) {
            ulonglong2 kA = *reinterpret_cast<const ulonglong2*>(kro + i * KTRS);      // (t0,t1),(t2,t3)
            ulonglong2 kB = *reinterpret_cast<const ulonglong2*>(kro + i * KTRS + 4);  // (t4,t5),(t6,t7)
            const float* wrow = wro + i * WIS;
            float4 w0 = *reinterpret_cast<const float4*>(wrow);
            float4 w1 = *reinterpret_cast<const float4*>(wrow + 4);
            float2 w2v = *reinterpret_cast<const float2*>(wrow + 8);
            float wsc[10] = {w0.x, w0.y, w0.z, w0.w, w1.x, w1.y, w1.z, w1.w, w2v.x, w2v.y};
            #pragma unroll
            for (int j = 0; j < 10; j++) {
                ull wd = pack2(wsc[j], wsc[j]);
                fma2(h[j],      kA.x, wd);
                fma2(h[10 + j], kA.y, wd);
                fma2(h[20 + j], kB.x, wd);
                fma2(h[30 + j], kB.y, wd);
            }
        }
    }
    __syncthreads();   // ktr + weff dead; safe to overwrite with h1T

    // ---------------- PReLU 1 + permuted transpose store: row pj = j*8 + JS ----------------
    {
        #pragma unroll
        for (int tp = 0; tp < 4; tp++) {
            int ta = t0 + 2 * tp;
            const float2* pL = reinterpret_cast<const float2*>(a1 + ta * H1 + 10 * JS);
            const float2* pH = reinterpret_cast<const float2*>(a1 + (ta + 1) * H1 + 10 * JS);
            float2 aL[5], aH[5];
            #pragma unroll
            for (int p = 0; p < 5; p++) { aL[p] = __ldg(pL + p); aH[p] = __ldg(pH + p); }
            float al[10] = {aL[0].x, aL[0].y, aL[1].x, aL[1].y, aL[2].x, aL[2].y, aL[3].x, aL[3].y, aL[4].x, aL[4].y};
            float ah[10] = {aH[0].x, aH[0].y, aH[1].x, aH[1].y, aH[2].x, aH[2].y, aH[3].x, aH[3].y, aH[4].x, aH[4].y};
            #pragma unroll
            for (int j = 0; j < 10; j++) {
                float x0, x1; unpack2(h[tp * 10 + j], x0, x1);
                x0 = (x0 > 0.f) ? x0 : al[j] * x0;
                x1 = (x1 > 0.f) ? x1 : ah[j] * x1;
                int pj = j * 8 + JS;
                *reinterpret_cast<float2*>(sm + OFF_H1T + pj * H1TS + ta) = make_float2(x0, x1);
            }
        }
    }
    __syncthreads();

    // ---------------- Layer 2: 8t x 5j2 tile over permuted rows ----------------
    float lg[8];
    {
        ull g[20];   // g[tp*5 + c]
        const float* b2p = sm + OFF_B2 + 5 * JS;
        #pragma unroll
        for (int c = 0; c < 5; c++) {
            float bv = b2p[c];
            ull bb2 = pack2(bv, bv);
            g[c] = bb2; g[5 + c] = bb2; g[10 + c] = bb2; g[15 + c] = bb2;
        }
        const float* hb  = sm + OFF_H1T + t0;
        const float* w2b = sm + OFF_W2P + 5 * JS;
        #pragma unroll 2
        for (int pj = 0; pj < H1; pj++) {
            ulonglong2 hA = *reinterpret_cast<const ulonglong2*>(hb + pj * H1TS);      // (t0,t1),(t2,t3)
            ulonglong2 hB = *reinterpret_cast<const ulonglong2*>(hb + pj * H1TS + 4);  // (t4,t5),(t6,t7)
            const float* wp = w2b + pj * H2;
            #pragma unroll
            for (int c = 0; c < 5; c++) {
                float wv = wp[c];
                ull ww = pack2(wv, wv);
                fma2(g[c],      hA.x, ww);
                fma2(g[5 + c],  hA.y, ww);
                fma2(g[10 + c], hB.x, ww);
                fma2(g[15 + c], hB.y, ww);
            }
        }

        // PReLU 2 + final dot -> per-(t, JS) partial logits
        float wfr[5];
        #pragma unroll
        for (int c = 0; c < 5; c++) wfr[c] = sm[OFF_WF + 5 * JS + c];
        #pragma unroll
        for (int tp = 0; tp < 4; tp++) {
            int ta = t0 + 2 * tp;
            const float* a2a = a2 + ta * H2 + 5 * JS;
            float la = 0.f, lb = 0.f;
            #pragma unroll
            for (int c = 0; c < 5; c++) {
                float p0 = __ldg(a2a + c);
                float p1 = __ldg(a2a + H2 + c);
                float x0, x1; unpack2(g[tp * 5 + c], x0, x1);
                x0 = (x0 > 0.f) ? x0 : p0 * x0;
                x1 = (x1 > 0.f) ? x1 : p1 * x1;
                la += x0 * wfr[c]; lb += x1 * wfr[c];
            }
            lg[2 * tp] = la; lg[2 * tp + 1] = lb;
        }
        // reduce over the 8 JS lanes (quarter-warp; quarters are TG-homogeneous)
        const unsigned qmask = 0xFFu << ((lane >> 3) << 3);
        #pragma unroll
        for (int o = 1; o < 8; o <<= 1) {
            #pragma unroll
            for (int r = 0; r < 8; r++)
                lg[r] += __shfl_xor_sync(qmask, lg[r], o);
        }
        if (JS == 0 && TG < TT / 8) {
            float bfv = sm[OFF_BF];
            *reinterpret_cast<float4*>(lbuf + t0) =
                make_float4(lg[0] + bfv, lg[1] + bfv, lg[2] + bfv, lg[3] + bfv);
            *reinterpret_cast<float4*>(lbuf + t0 + 4) =
                make_float4(lg[4] + bfv, lg[5] + bfv, lg[6] + bfv, lg[7] + bfv);
        }
    }
    __syncthreads();

    // ---------------- Softmax over T (224 threads, 7 warps) ----------------
    const bool valid = (tid < TT);
    float logit = valid ? lbuf[tid] : -3.4e38f;
    float x = logit;
    #pragma unroll
    for (int o = 16; o; o >>= 1) x = fmaxf(x, __shfl_xor_sync(0xffffffffu, x, o));
    if (lane == 0) rbuf[warp] = x;
    __syncthreads();
    if (warp == 0) {
        float y = (lane < 7) ? rbuf[lane] : -3.4e38f;
        #pragma unroll
        for (int o = 4; o; o >>= 1) y = fmaxf(y, __shfl_xor_sync(0xffffffffu, y, o));
        if (lane == 0) rbuf[0] = y;
    }
    __syncthreads();
    const float m = rbuf[0];

    float e = valid ? __expf(logit - m) : 0.f;
    float s = e;
    #pragma unroll
    for (int o = 16; o; o >>= 1) s += __shfl_xor_sync(0xffffffffu, s, o);
    if (lane == 0) rbuf[16 + warp] = s;
    __syncthreads();
    if (warp == 0) {
        float y = (lane < 7) ? rbuf[16 + lane] : 0.f;
        #pragma unroll
        for (int o = 4; o; o >>= 1) y += __shfl_xor_sync(0xffffffffu, y, o);
        if (lane == 0) rbuf[16] = y;
    }
    __syncthreads();
    const float inv = 1.f / rbuf[16];
    if (valid) lbuf[tid] = e * inv;
    __syncthreads();

    // ---------------- out[b][d] = sum_t w[t] * v[b][t][d] ----------------
    if (tid < 192) {
        const int d   = tid & 63;
        const int grp = tid >> 6;   // 0..2
        const float* vb = v + (size_t)b * TT * DD;
        float acc = 0.f;
        #pragma unroll 4
        for (int t2 = grp; t2 < TT; t2 += 3)
            acc += lbuf[t2] * vb[t2 * DD + d];
        vpart[tid] = acc;
    }
    __syncthreads();
    if (tid < DD) {
        out[(size_t)b * DD + tid] =
            vpart[tid] + vpart[64 + tid] + vpart[128 + tid];
    }
}

extern "C" void kernel_launch(void* const* d_in, const int* in_sizes, int n_in,
                              void* d_out, int out_size)
{
    const float* q  = (const float*)d_in[0];
    const float* k  = (const float*)d_in[1];
    const float* v  = (const float*)d_in[2];
    const float* W1 = (const float*)d_in[3];
    const float* b1 = (const float*)d_in[4];
    const float* a1 = (const float*)d_in[5];
    const float* W2 = (const float*)d_in[6];
    const float* b2 = (const float*)d_in[7];
    const float* a2 = (const float*)d_in[8];
    const float* Wf = (const float*)d_in[9];
    const float* bf = (const float*)d_in[10];
    float* out = (float*)d_out;

    cudaFuncSetAttribute(din_attention_kernel,
                         cudaFuncAttributeMaxDynamicSharedMemorySize, SMEM_BYTES);
    din_attention_kernel<<<BB, NTHR, SMEM_BYTES>>>(q, k, v, W1, b1, a1, W2, b2, a2, Wf, bf, out);
}

// round 8
// speedup vs baseline: 1.8435x; 1.0893x over previous
#include <cuda_runtime.h>
#include <math.h>

// Problem constants
#define BB 2048
#define TT 200
#define DD 64
#define H1 80
#define H2 40
#define NTHR 288

#define KTRS 204   // k_tr i-row stride (floats): even -> 8B-aligned ull loads
#define WES  772   // weff slot stride: %4==0, 772%32=4 -> banks 4*JS distinct
#define WIS  12    // weff i-stride within slot (10 data + 2 pad)
#define H1TS 204   // h1T row stride

// Shared memory layout (float offsets)
#define OFF_KTR   0        // 64*204 = 13056
#define OFF_WEFF  13056    // 8*772 = 6176 -> 19232
#define OFF_H1T   0        // 80*204 = 16320, aliases ktr (+weff head); both dead after layer 1
#define OFF_W2P   19232    // 3200 -> 22432 (row-permuted W2)
#define OFF_Q     22432    // 64
#define OFF_C     22496    // 80
#define OFF_CP    22576    // 160
#define OFF_WF    22736    // 40
#define OFF_B2    22776    // 40
#define OFF_BF    22816    // 8
#define OFF_LBUF  22824    // 208
#define OFF_RBUF  23032    // 32
#define OFF_VPART 23064    // 256
#define SMEM_FLOATS 23320
#define SMEM_BYTES  (SMEM_FLOATS * 4)

typedef unsigned long long ull;

// ---- packed f32x2 helpers (sm_100+; ptxas never auto-fuses) ----
__device__ __forceinline__ ull pack2(float lo, float hi) {
    ull r;
    asm("mov.b64 %0, {%1, %2};" : "=l"(r) : "r"(__float_as_uint(lo)), "r"(__float_as_uint(hi)));
    return r;
}
__device__ __forceinline__ void unpack2(ull v, float& lo, float& hi) {
    unsigned int a, b;
    asm("mov.b64 {%0, %1}, %2;" : "=r"(a), "=r"(b) : "l"(v));
    lo = __uint_as_float(a);
    hi = __uint_as_float(b);
}
__device__ __forceinline__ void fma2(ull& d, ull a, ull b) {
    asm("fma.rn.f32x2 %0, %1, %2, %0;" : "+l"(d) : "l"(a), "l"(b));
}

__global__ void __launch_bounds__(NTHR, 2)
din_attention_kernel(const float* __restrict__ q,
                     const float* __restrict__ k,
                     const float* __restrict__ v,
                     const float* __restrict__ W1,
                     const float* __restrict__ b1,
                     const float* __restrict__ a1,
                     const float* __restrict__ W2,
                     const float* __restrict__ b2,
                     const float* __restrict__ a2,
                     const float* __restrict__ Wf,
                     const float* __restrict__ bf,
                     float* __restrict__ out)
{
    extern __shared__ float sm[];
    float* lbuf  = sm + OFF_LBUF;
    float* rbuf  = sm + OFF_RBUF;
    float* vpart = sm + OFF_VPART;

    const int tid  = threadIdx.x;
    const int b    = blockIdx.x;
    const int lane = tid & 31;
    const int warp = tid >> 5;

    const int TG  = tid >> 3;                        // t-group 0..35 (6 t each)
    const int JS  = tid & 7;                         // j-slot 0..7 (10 j1 each)
    const int NTG = 34;                              // ceil(200/6)
    const int TGC = (TG < NTG) ? TG : (NTG - 1);
    const int t0  = 6 * TGC;

    // ---------------- Phase A: stage data ----------------
    if (tid < DD) sm[OFF_Q + tid] = q[(size_t)b * DD + tid];
    {
        // k -> k_tr[i][t] transpose (coalesced reads)
        const float* kb = k + (size_t)b * TT * DD;
        #pragma unroll 4
        for (int x = tid; x < TT * DD; x += NTHR) {
            int t = x >> 6, i = x & 63;
            sm[OFF_KTR + i * KTRS + t] = kb[x];
        }
    }
    {
        // W2 -> row-permuted w2p: physical row pj holds logical j1 = 10*(pj%8) + pj/8
        for (int x = tid; x < H1 * H2; x += NTHR) {
            int pj = x / H2, j2 = x - pj * H2;
            int j1 = 10 * (pj & 7) + (pj >> 3);
            sm[OFF_W2P + x] = W2[j1 * H2 + j2];
        }
    }
    if (tid < H2) sm[OFF_WF + tid] = Wf[tid];
    if (tid >= 64 && tid < 64 + H2) sm[OFF_B2 + tid - 64] = b2[tid - 64];
    if (tid == 104) sm[OFF_BF] = bf[0];
    __syncthreads();   // q ready

    // ---------------- Phase B: weff + c partials ----------------
    // weff[slot js][i][jj] for j1 = 10*js + jj
    #pragma unroll 4
    for (int x = tid; x < DD * H1; x += NTHR) {
        int i = x / H1;
        int j = x - i * H1;
        float w = W1[(DD + i) * H1 + j]
                - W1[(2 * DD + i) * H1 + j]
                + sm[OFF_Q + i] * W1[(3 * DD + i) * H1 + j];
        sm[OFF_WEFF + (j / 10) * WES + i * WIS + (j % 10)] = w;
    }
    if (tid < 160) {
        int j  = tid % 80;
        int ch = tid / 80;          // 0..1
        float c = 0.f;
        #pragma unroll
        for (int i = ch * 32; i < ch * 32 + 32; i++)
            c += sm[OFF_Q + i] * (W1[i * H1 + j] + W1[(2 * DD + i) * H1 + j]);
        sm[OFF_CP + ch * 80 + j] = c;
    }
    __syncthreads();
    if (tid < H1)
        sm[OFF_C + tid] = b1[tid] + sm[OFF_CP + tid] + sm[OFF_CP + 80 + tid];
    __syncthreads();

    // ---------------- Layer 1: 6t x 10j tile, h packed over t-pairs ----------------
    ull h[30];   // h[tp*10 + j], tp = t-pair 0..2, j1 = 10*JS + j
    {
        const float* cb = sm + OFF_C + 10 * JS;
        #pragma unroll
        for (int j = 0; j < 10; j++) {
            float cv = cb[j];
            ull cc = pack2(cv, cv);
            h[j] = cc; h[10 + j] = cc; h[20 + j] = cc;
        }
    }
    {
        const float* kro = sm + OFF_KTR + t0;
        const float* wro = sm + OFF_WEFF + JS * WES;
        #pragma unroll 2
        for (int i = 0; i < DD; i++) {
            const ull* kp = reinterpret_cast<const ull*>(kro + i * KTRS);
            ull k01 = kp[0], k23 = kp[1], k45 = kp[2];
            const float* wrow = wro + i * WIS;
            float4 w0 = *reinterpret_cast<const float4*>(wrow);
            float4 w1 = *reinterpret_cast<const float4*>(wrow + 4);
            float2 w2v = *reinterpret_cast<const float2*>(wrow + 8);
            float wsc[10] = {w0.x, w0.y, w0.z, w0.w, w1.x, w1.y, w1.z, w1.w, w2v.x, w2v.y};
            #pragma unroll
            for (int j = 0; j < 10; j++) {
                ull wd = pack2(wsc[j], wsc[j]);
                fma2(h[j],      k01, wd);
                fma2(h[10 + j], k23, wd);
                fma2(h[20 + j], k45, wd);
            }
        }
    }
    __syncthreads();   // ktr + weff dead; safe to overwrite with h1T

    // ---------------- PReLU 1 + permuted transpose store: row pj = j*8 + JS ----------------
    {
        #pragma unroll
        for (int tp = 0; tp < 3; tp++) {
            int ta = t0 + 2 * tp;
            const float2* pL = reinterpret_cast<const float2*>(a1 + ta * H1 + 10 * JS);
            const float2* pH = reinterpret_cast<const float2*>(a1 + (ta + 1) * H1 + 10 * JS);
            float2 aL[5], aH[5];
            #pragma unroll
            for (int p = 0; p < 5; p++) { aL[p] = __ldg(pL + p); aH[p] = __ldg(pH + p); }
            float al[10] = {aL[0].x, aL[0].y, aL[1].x, aL[1].y, aL[2].x, aL[2].y, aL[3].x, aL[3].y, aL[4].x, aL[4].y};
            float ah[10] = {aH[0].x, aH[0].y, aH[1].x, aH[1].y, aH[2].x, aH[2].y, aH[3].x, aH[3].y, aH[4].x, aH[4].y};
            #pragma unroll
            for (int j = 0; j < 10; j++) {
                float x0, x1; unpack2(h[tp * 10 + j], x0, x1);
                x0 = (x0 > 0.f) ? x0 : al[j] * x0;
                x1 = (x1 > 0.f) ? x1 : ah[j] * x1;
                int pj = j * 8 + JS;
                *reinterpret_cast<float2*>(sm + OFF_H1T + pj * H1TS + ta) = make_float2(x0, x1);
            }
        }
    }
    __syncthreads();

    // ---------------- Layer 2: 6t x 5j2 tile over permuted rows ----------------
    float lg[6];
    {
        ull g[15];   // g[tp*5 + c]
        const float* b2p = sm + OFF_B2 + 5 * JS;
        #pragma unroll
        for (int c = 0; c < 5; c++) {
            float bv = b2p[c];
            ull bb2 = pack2(bv, bv);
            g[c] = bb2; g[5 + c] = bb2; g[10 + c] = bb2;
        }
        const float* hb  = sm + OFF_H1T + t0;
        const float* w2b = sm + OFF_W2P + 5 * JS;
        #pragma unroll 2
        for (int pj = 0; pj < H1; pj++) {
            const ull* hp = reinterpret_cast<const ull*>(hb + pj * H1TS);
            ull hA = hp[0], hB = hp[1], hC = hp[2];
            const float* wp = w2b + pj * H2;
            #pragma unroll
            for (int c = 0; c < 5; c++) {
                float wv = wp[c];
                ull ww = pack2(wv, wv);
                fma2(g[c],      hA, ww);
                fma2(g[5 + c],  hB, ww);
                fma2(g[10 + c], hC, ww);
            }
        }

        // PReLU 2 + final dot -> per-(t, JS) partial logits
        float wfr[5];
        #pragma unroll
        for (int c = 0; c < 5; c++) wfr[c] = sm[OFF_WF + 5 * JS + c];
        #pragma unroll
        for (int tp = 0; tp < 3; tp++) {
            int ta = t0 + 2 * tp;
            const float* a2a = a2 + ta * H2 + 5 * JS;
            float la = 0.f, lb = 0.f;
            #pragma unroll
            for (int c = 0; c < 5; c++) {
                float p0 = __ldg(a2a + c);
                float p1 = __ldg(a2a + H2 + c);
                float x0, x1; unpack2(g[tp * 5 + c], x0, x1);
                x0 = (x0 > 0.f) ? x0 : p0 * x0;
                x1 = (x1 > 0.f) ? x1 : p1 * x1;
                la += x0 * wfr[c]; lb += x1 * wfr[c];
            }
            lg[2 * tp] = la; lg[2 * tp + 1] = lb;
        }
        // reduce over the 8 JS lanes (quarter-warp; quarters are TG-homogeneous)
        const unsigned qmask = 0xFFu << ((lane >> 3) << 3);
        #pragma unroll
        for (int o = 1; o < 8; o <<= 1) {
            #pragma unroll
            for (int r = 0; r < 6; r++)
                lg[r] += __shfl_xor_sync(qmask, lg[r], o);
        }
        if (JS == 0 && TG < NTG) {
            float bfv = sm[OFF_BF];
            *reinterpret_cast<float2*>(lbuf + t0)     = make_float2(lg[0] + bfv, lg[1] + bfv);
            *reinterpret_cast<float2*>(lbuf + t0 + 2) = make_float2(lg[2] + bfv, lg[3] + bfv);
            *reinterpret_cast<float2*>(lbuf + t0 + 4) = make_float2(lg[4] + bfv, lg[5] + bfv);
        }
    }
    __syncthreads();

    // ---------------- Softmax over T (288 threads, 9 warps) ----------------
    const bool valid = (tid < TT);
    float logit = valid ? lbuf[tid] : -3.4e38f;
    float x = logit;
    #pragma unroll
    for (int o = 16; o; o >>= 1) x = fmaxf(x, __shfl_xor_sync(0xffffffffu, x, o));
    if (lane == 0) rbuf[warp] = x;
    __syncthreads();
    if (warp == 0) {
        float y = (lane < 9) ? rbuf[lane] : -3.4e38f;
        #pragma unroll
        for (int o = 8; o; o >>= 1) y = fmaxf(y, __shfl_xor_sync(0xffffffffu, y, o));
        if (lane == 0) rbuf[0] = y;
    }
    __syncthreads();
    const float m = rbuf[0];

    float e = valid ? __expf(logit - m) : 0.f;
    float s = e;
    #pragma unroll
    for (int o = 16; o; o >>= 1) s += __shfl_xor_sync(0xffffffffu, s, o);
    if (lane == 0) rbuf[16 + warp] = s;
    __syncthreads();
    if (warp == 0) {
        float y = (lane < 9) ? rbuf[16 + lane] : 0.f;
        #pragma unroll
        for (int o = 8; o; o >>= 1) y += __shfl_xor_sync(0xffffffffu, y, o);
        if (lane == 0) rbuf[16] = y;
    }
    __syncthreads();
    const float inv = 1.f / rbuf[16];
    if (valid) lbuf[tid] = e * inv;
    __syncthreads();

    // ---------------- out[b][d] = sum_t w[t] * v[b][t][d] ----------------
    if (tid < 256) {
        const int d   = tid & 63;
        const int grp = tid >> 6;   // 0..3
        const float* vb = v + (size_t)b * TT * DD;
        float acc = 0.f;
        #pragma unroll 5
        for (int t2 = grp; t2 < TT; t2 += 4)
            acc += lbuf[t2] * vb[t2 * DD + d];
        vpart[tid] = acc;
    }
    __syncthreads();
    if (tid < DD) {
        out[(size_t)b * DD + tid] =
            vpart[tid] + vpart[64 + tid] + vpart[128 + tid] + vpart[192 + tid];
    }
}

extern "C" void kernel_launch(void* const* d_in, const int* in_sizes, int n_in,
                              void* d_out, int out_size)
{
    const float* q  = (const float*)d_in[0];
    const float* k  = (const float*)d_in[1];
    const float* v  = (const float*)d_in[2];
    const float* W1 = (const float*)d_in[3];
    const float* b1 = (const float*)d_in[4];
    const float* a1 = (const float*)d_in[5];
    const float* W2 = (const float*)d_in[6];
    const float* b2 = (const float*)d_in[7];
    const float* a2 = (const float*)d_in[8];
    const float* Wf = (const float*)d_in[9];
    const float* bf = (const float*)d_in[10];
    float* out = (float*)d_out;

    cudaFuncSetAttribute(din_attention_kernel,
                         cudaFuncAttributeMaxDynamicSharedMemorySize, SMEM_BYTES);
    din_attention_kernel<<<BB, NTHR, SMEM_BYTES>>>(q, k, v, W1, b1, a1, W2, b2, a2, Wf, bf, out);
}